// round 1
// baseline (speedup 1.0000x reference)
#include <cuda_runtime.h>
#include <math.h>

// ---------------- problem constants ----------------
constexpr int R    = 4096;   // proposals
constexpr int D    = 4096;   // feature dim
constexpr int C    = 20;     // classes (after dropping last)
constexpr int NC   = 21;     // C + 1
constexpr float IMG_W = 1216.0f;
constexpr float IMG_H = 800.0f;
constexpr float SCORE_THRESH = 0.05f;
constexpr float NMS_THRESH   = 0.5f;
constexpr int TOPK = 100;

// ---------------- GEMM tiling ----------------
constexpr int KSPLIT = 4;
constexpr int BM     = 64;             // rows per block
constexpr int ROWBLOCKS = R / BM;      // 64
constexpr int NPAD   = 48;             // 42 cols padded to 48
constexpr int TM     = 4;
constexpr int TN     = 4;
constexpr int RT     = BM / TM;        // 16
constexpr int CT     = NPAD / TN;      // 12
constexpr int NTH    = RT * CT;        // 192 threads
constexpr int KC     = 32;             // K chunk
constexpr int KPB    = D / KSPLIT;     // 1024 K per block

// ---------------- device scratch (static: no allocs allowed) ----------------
__device__ float g_part[KSPLIT][R * NPAD];   // GEMM partial sums
__device__ float g_cls[R * NC];
__device__ float g_det[R * NC];
__device__ float g_colmax[NC];
__device__ float g_colsum[NC];
__device__ float g_scores[R * C];
__device__ float4 g_bclip[R];
__device__ float g_kept[R * C];
__device__ int   g_ncand;
__device__ float g_cand_val[R * C];
__device__ int   g_cand_idx[R * C];
__device__ int   g_sidx[C][R];
__device__ float g_sval[C][R];
__device__ int   g_sorder[C][R];

// ---------------- helpers ----------------
__device__ __forceinline__ float iou_f(float4 a, float4 b) {
    float areaA = (a.z - a.x) * (a.w - a.y);
    float areaB = (b.z - b.x) * (b.w - b.y);
    float lx = fmaxf(a.x, b.x), ly = fmaxf(a.y, b.y);
    float rx = fminf(a.z, b.z), ry = fminf(a.w, b.w);
    float w = fmaxf(rx - lx, 0.f), h = fmaxf(ry - ly, 0.f);
    float inter = w * h;
    return inter / (areaA + areaB - inter + 1e-9f);
}

// ---------------- kernels ----------------
__global__ void k_init() {
    int i = blockIdx.x * blockDim.x + threadIdx.x;
    if (i < R * C) g_kept[i] = 0.f;
    if (i == 0) g_ncand = 0;
}

// dual GEMM: logits = x @ [W_cls | W_det], K-split partials
__global__ __launch_bounds__(NTH) void k_gemm(const float* __restrict__ x,
                                              const float* __restrict__ Wc,
                                              const float* __restrict__ Wd) {
    __shared__ float xs[KC][BM];
    __shared__ float ws[KC][NPAD];
    const int rb  = blockIdx.x;
    const int ks  = blockIdx.y;
    const int tid = threadIdx.x;
    const int rt  = tid / CT;
    const int ct  = tid % CT;
    const int row0  = rb * BM;
    const int kbase = ks * KPB;

    float acc[TM][TN];
#pragma unroll
    for (int i = 0; i < TM; i++)
#pragma unroll
        for (int j = 0; j < TN; j++) acc[i][j] = 0.f;

    // zero the padded W columns (42..47) once; never overwritten afterwards
    for (int q = tid; q < KC * (NPAD - 2 * NC); q += NTH) {
        int kk = q / (NPAD - 2 * NC);
        int j  = q % (NPAD - 2 * NC);
        ws[kk][2 * NC + j] = 0.f;
    }

    for (int kc = 0; kc < KPB; kc += KC) {
        const int k0 = kbase + kc;
        __syncthreads();
        // stage x chunk transposed: xs[k][row]
        for (int q = tid; q < BM * (KC / 4); q += NTH) {
            int r  = q / (KC / 4);
            int kq = q % (KC / 4);
            float4 v = *reinterpret_cast<const float4*>(
                &x[(size_t)(row0 + r) * D + k0 + kq * 4]);
            xs[kq * 4 + 0][r] = v.x;
            xs[kq * 4 + 1][r] = v.y;
            xs[kq * 4 + 2][r] = v.z;
            xs[kq * 4 + 3][r] = v.w;
        }
        // stage W chunk: cols 0..20 = W_cls, 21..41 = W_det
        for (int q = tid; q < KC * NC; q += NTH) {
            int kk = q / NC;
            int c  = q % NC;
            ws[kk][c]      = Wc[(size_t)(k0 + kk) * NC + c];
            ws[kk][NC + c] = Wd[(size_t)(k0 + kk) * NC + c];
        }
        __syncthreads();
#pragma unroll 8
        for (int kk = 0; kk < KC; kk++) {
            float4 xv = *reinterpret_cast<const float4*>(&xs[kk][rt * TM]);
            float4 wv = *reinterpret_cast<const float4*>(&ws[kk][ct * TN]);
            float xr[4] = {xv.x, xv.y, xv.z, xv.w};
            float wr[4] = {wv.x, wv.y, wv.z, wv.w};
#pragma unroll
            for (int i = 0; i < TM; i++)
#pragma unroll
                for (int j = 0; j < TN; j++)
                    acc[i][j] = fmaf(xr[i], wr[j], acc[i][j]);
        }
    }
    float* dst = &g_part[ks][0];
#pragma unroll
    for (int i = 0; i < TM; i++) {
        int row = row0 + rt * TM + i;
#pragma unroll
        for (int j = 0; j < TN; j++)
            dst[(size_t)row * NPAD + ct * TN + j] = acc[i][j];
    }
}

// combine K-split partials + bias -> cls/det logits
__global__ void k_reduce(const float* __restrict__ b_cls,
                         const float* __restrict__ b_det) {
    int i = blockIdx.x * blockDim.x + threadIdx.x;
    if (i >= R * 2 * NC) return;
    int row = i / (2 * NC);
    int c   = i % (2 * NC);
    float s = 0.f;
#pragma unroll
    for (int ks = 0; ks < KSPLIT; ks++) s += g_part[ks][(size_t)row * NPAD + c];
    if (c < NC) g_cls[row * NC + c] = s + b_cls[c];
    else        g_det[row * NC + (c - NC)] = s + b_det[c - NC];
}

// column softmax stats for det logits (softmax over rows, per column)
__global__ __launch_bounds__(256) void k_colred() {
    __shared__ float red[256];
    const int c   = blockIdx.x;
    const int tid = threadIdx.x;
    float m = -1e30f;
    for (int r = tid; r < R; r += 256) m = fmaxf(m, g_det[r * NC + c]);
    red[tid] = m; __syncthreads();
    for (int s = 128; s > 0; s >>= 1) {
        if (tid < s) red[tid] = fmaxf(red[tid], red[tid + s]);
        __syncthreads();
    }
    m = red[0]; __syncthreads();
    float sum = 0.f;
    for (int r = tid; r < R; r += 256) sum += expf(g_det[r * NC + c] - m);
    red[tid] = sum; __syncthreads();
    for (int s = 128; s > 0; s >>= 1) {
        if (tid < s) red[tid] += red[tid + s];
        __syncthreads();
    }
    if (tid == 0) { g_colmax[c] = m; g_colsum[c] = red[0]; }
}

// scores = row_softmax(cls) * col_softmax(det), drop last col; clip boxes
__global__ __launch_bounds__(256) void k_scores(const float* __restrict__ boxes) {
    int row = blockIdx.x * blockDim.x + threadIdx.x;
    if (row >= R) return;
    float cl[NC];
    float rm = -1e30f;
#pragma unroll
    for (int c = 0; c < NC; c++) {
        cl[c] = g_cls[row * NC + c];
        rm = fmaxf(rm, cl[c]);
    }
    float rs = 0.f;
#pragma unroll
    for (int c = 0; c < NC; c++) { cl[c] = expf(cl[c] - rm); rs += cl[c]; }
    float inv = 1.f / rs;
#pragma unroll
    for (int c = 0; c < C; c++) {
        float det = expf(g_det[row * NC + c] - g_colmax[c]) / g_colsum[c];
        g_scores[row * C + c] = cl[c] * inv * det;
    }
    float x1 = fminf(fmaxf(boxes[row * 4 + 0], 0.f), IMG_W);
    float y1 = fminf(fmaxf(boxes[row * 4 + 1], 0.f), IMG_H);
    float x2 = fminf(fmaxf(boxes[row * 4 + 2], 0.f), IMG_W);
    float y2 = fminf(fmaxf(boxes[row * 4 + 3], 0.f), IMG_H);
    g_bclip[row] = make_float4(x1, y1, x2, y2);
}

// per-class greedy NMS (one block per class)
__global__ __launch_bounds__(256) void k_nms() {
    __shared__ int scnt;
    __shared__ unsigned char ssupp[R];
    const int cls = blockIdx.x;
    const int tid = threadIdx.x;
    if (tid == 0) scnt = 0;
    __syncthreads();
    // gather candidates above the score threshold
    for (int r = tid; r < R; r += 256) {
        float v = g_scores[r * C + cls];
        if (v > SCORE_THRESH) {
            int p = atomicAdd(&scnt, 1);
            g_sidx[cls][p] = r;
            g_sval[cls][p] = v;
        }
    }
    __syncthreads();
    const int m = scnt;
    if (m == 0) return;
    // rank sort: descending score, tie -> lower proposal index (argsort(-sc) stable)
    for (int i = tid; i < m; i += 256) {
        float vi = g_sval[cls][i];
        int   ri = g_sidx[cls][i];
        int rank = 0;
        for (int j = 0; j < m; j++) {
            float vj = g_sval[cls][j];
            int   rj = g_sidx[cls][j];
            if (vj > vi || (vj == vi && rj < ri)) rank++;
        }
        g_sorder[cls][rank] = i;
    }
    for (int q = tid; q < m; q += 256) ssupp[q] = 0;
    __syncthreads();
    // sequential greedy with parallel suppression
    for (int pos = 0; pos < m; pos++) {
        if (!ssupp[pos]) {
            int   i = g_sorder[cls][pos];
            int   r = g_sidx[cls][i];
            float v = g_sval[cls][i];
            if (tid == 0) {
                g_kept[r * C + cls] = v;
                int p = atomicAdd(&g_ncand, 1);
                g_cand_val[p] = v;
                g_cand_idx[p] = r * C + cls;
            }
            float4 bi = g_bclip[r];
            for (int q = pos + 1 + tid; q < m; q += 256) {
                if (!ssupp[q]) {
                    int j = g_sorder[cls][q];
                    float4 bj = g_bclip[g_sidx[cls][j]];
                    if (iou_f(bi, bj) > NMS_THRESH) ssupp[q] = 1;
                }
            }
        }
        __syncthreads();
    }
}

// top-100 with jax.lax.top_k tie semantics; output = [vals | boxes | cls]
__global__ __launch_bounds__(256) void k_final(float* __restrict__ out) {
    __shared__ float bv[256];
    __shared__ int   bfi[256];
    __shared__ int   bps[256];
    const int tid = threadIdx.x;
    int n = g_ncand;
    if (n > R * C) n = R * C;
    int take = n < TOPK ? n : TOPK;
    for (int round = 0; round < take; round++) {
        float best = -2.f; int bestfi = 0x7fffffff; int bestp = -1;
        for (int p = tid; p < n; p += 256) {
            float v = g_cand_val[p];
            if (v < 0.f) continue;  // already taken
            int fi = g_cand_idx[p];
            if (v > best || (v == best && fi < bestfi)) {
                best = v; bestfi = fi; bestp = p;
            }
        }
        bv[tid] = best; bfi[tid] = bestfi; bps[tid] = bestp;
        __syncthreads();
        for (int s = 128; s > 0; s >>= 1) {
            if (tid < s) {
                if (bv[tid + s] > bv[tid] ||
                    (bv[tid + s] == bv[tid] && bfi[tid + s] < bfi[tid])) {
                    bv[tid] = bv[tid + s];
                    bfi[tid] = bfi[tid + s];
                    bps[tid] = bps[tid + s];
                }
            }
            __syncthreads();
        }
        if (tid == 0) {
            int fi = bfi[0];
            int prop = fi / C, cl = fi % C;
            float4 b = g_bclip[prop];
            out[round] = bv[0];
            out[TOPK + round * 4 + 0] = b.x;
            out[TOPK + round * 4 + 1] = b.y;
            out[TOPK + round * 4 + 2] = b.z;
            out[TOPK + round * 4 + 3] = b.w;
            out[TOPK + TOPK * 4 + round] = (float)cl;
            g_cand_val[bps[0]] = -1.f;
        }
        __syncthreads();
    }
    // fill remaining slots with zeros: lowest flat indices among non-kept
    if (tid == 0) {
        int slot = take;
        int i = 0;
        while (slot < TOPK && i < R * C) {
            if (g_kept[i] == 0.f) {
                int prop = i / C, cl = i % C;
                float4 b = g_bclip[prop];
                out[slot] = 0.f;
                out[TOPK + slot * 4 + 0] = b.x;
                out[TOPK + slot * 4 + 1] = b.y;
                out[TOPK + slot * 4 + 2] = b.z;
                out[TOPK + slot * 4 + 3] = b.w;
                out[TOPK + TOPK * 4 + slot] = (float)cl;
                slot++;
            }
            i++;
        }
    }
}

extern "C" void kernel_launch(void* const* d_in, const int* in_sizes, int n_in,
                              void* d_out, int out_size) {
    const float* x     = (const float*)d_in[0];
    const float* boxes = (const float*)d_in[1];
    const float* W_cls = (const float*)d_in[2];
    const float* b_cls = (const float*)d_in[3];
    const float* W_det = (const float*)d_in[4];
    const float* b_det = (const float*)d_in[5];
    float* out = (float*)d_out;

    k_init<<<(R * C + 255) / 256, 256>>>();
    dim3 gg(ROWBLOCKS, KSPLIT);
    k_gemm<<<gg, NTH>>>(x, W_cls, W_det);
    k_reduce<<<(R * 2 * NC + 255) / 256, 256>>>(b_cls, b_det);
    k_colred<<<NC, 256>>>();
    k_scores<<<(R + 255) / 256, 256>>>(boxes);
    k_nms<<<C, 256>>>();
    k_final<<<1, 256>>>(out);
}